// round 15
// baseline (speedup 1.0000x reference)
#include <cuda_runtime.h>
#include <cuda_fp16.h>
#include <cstdint>
#include <math.h>

#define E 8
#define TOPK 2
#define CAP 512
#define H 2048
#define F 8192
#define NSLOT (E*CAP)   // 4096

// ---------------- scratch (no allocation allowed) ----------------
__device__ __half g_xh[(size_t)2048 * H];     // fp16 copy of tokens
__device__ __half g_acth[(size_t)NSLOT * F];  // gelu acts fp16
__device__ __half g_w1h[(size_t)F * H];       // w1 fp16
__device__ __half g_w2h[(size_t)H * F];       // w2 fp16
__device__ float  g_h[(size_t)NSLOT * H];     // expert output fp32
__device__ __half g_zerorow[H];               // zero A-row for dropped slots
__device__ int    g_entry_expert[2 * 2048];
__device__ float  g_entry_prob  [2 * 2048];
__device__ int    g_entry_dest  [2 * 2048];   // dest slot or -1 (for combine)
__device__ int    g_slot_token  [NSLOT];      // token feeding each slot, or -1

// ---------------- helpers ----------------
__device__ __forceinline__ uint32_t smem_u32(const void* p) {
    uint32_t a;
    asm("{ .reg .u64 t; cvta.to.shared.u64 t, %1; cvt.u32.u64 %0, t; }"
        : "=r"(a) : "l"(p));
    return a;
}
__device__ __forceinline__ void cp16(uint32_t dst, const void* src) {
    asm volatile("cp.async.cg.shared.global [%0], [%1], 16;"
                 :: "r"(dst), "l"(src) : "memory");
}
__device__ __forceinline__ void ldsm_x4(uint32_t* r, uint32_t addr) {
    asm volatile("ldmatrix.sync.aligned.m8n8.x4.shared.b16 {%0,%1,%2,%3}, [%4];"
                 : "=r"(r[0]), "=r"(r[1]), "=r"(r[2]), "=r"(r[3]) : "r"(addr));
}
__device__ __forceinline__ void mma_f16(float* c, const uint32_t* a, const uint32_t* b) {
    asm volatile(
        "mma.sync.aligned.m16n8k16.row.col.f32.f16.f16.f32 "
        "{%0,%1,%2,%3}, {%4,%5,%6,%7}, {%8,%9}, {%0,%1,%2,%3};"
        : "+f"(c[0]), "+f"(c[1]), "+f"(c[2]), "+f"(c[3])
        : "r"(a[0]), "r"(a[1]), "r"(a[2]), "r"(a[3]), "r"(b[0]), "r"(b[1]));
}

// ---------------- fp32 -> fp16 conversion pass (weights) ----------------
__global__ void tohalf(const float* __restrict__ src, __half* __restrict__ dst,
                       size_t n4) {
    size_t i = (size_t)blockIdx.x * blockDim.x + threadIdx.x;
    if (i < n4) {
        float4 v = ((const float4*)src)[i];
        ((__half2*)dst)[2 * i]     = __floats2half2_rn(v.x, v.y);
        ((__half2*)dst)[2 * i + 1] = __floats2half2_rn(v.z, v.w);
    }
}

// ---------------- router: 16 tokens per block, rw staged in smem ----------------
#define RT 16
#define ROUTER_SMEM (E * H * 4 + RT * E * 4)

__global__ void router_kernel(const float* __restrict__ x,
                              const float* __restrict__ rw,
                              __half* __restrict__ xh, int N) {
    extern __shared__ float rsm[];
    float* rws = rsm;                 // [E][H]
    float* lg  = rsm + E * H;         // [RT][E]
    const int tid = threadIdx.x;
    const int lane = tid & 31, warp = tid >> 5;
    const int t0 = blockIdx.x * RT;

    for (int i = tid; i < E * H / 4; i += 256)
        ((float4*)rws)[i] = ((const float4*)rw)[i];
    __syncthreads();

    // warp w computes logits for expert w over the 16 tokens
    const float* wr = rws + warp * H;
    for (int tt = 0; tt < RT; tt++) {
        const float* xr = x + (size_t)(t0 + tt) * H;
        float s = 0.f;
        for (int i = lane; i < H; i += 32) s += __ldg(&xr[i]) * wr[i];
        #pragma unroll
        for (int o = 16; o; o >>= 1) s += __shfl_xor_sync(0xffffffffu, s, o);
        if (lane == 0) lg[tt * E + warp] = s;
    }
    __syncthreads();

    if (tid < RT) {
        const int t = t0 + tid;
        const float* l = lg + tid * E;
        float m = l[0];
        #pragma unroll
        for (int e = 1; e < E; e++) m = fmaxf(m, l[e]);
        float p[E], den = 0.f;
        #pragma unroll
        for (int e = 0; e < E; e++) { p[e] = __expf(l[e] - m); den += p[e]; }
        float inv = 1.f / den;
        #pragma unroll
        for (int e = 0; e < E; e++) p[e] *= inv;
        int i0 = 0;
        #pragma unroll
        for (int e = 1; e < E; e++) if (p[e] > p[i0]) i0 = e;
        int i1 = (i0 == 0) ? 1 : 0;
        #pragma unroll
        for (int e = 0; e < E; e++) if (e != i0 && p[e] > p[i1]) i1 = e;
        g_entry_expert[t]     = i0; g_entry_prob[t]     = p[i0];
        g_entry_expert[N + t] = i1; g_entry_prob[N + t] = p[i1];
    }

    // fp16 writeback of the 16 token rows (x is L2-hot)
    for (int u = tid; u < RT * H / 4; u += 256) {
        const int tt = u / (H / 4), i = u % (H / 4);
        float4 v = __ldg((const float4*)(x + (size_t)(t0 + tt) * H) + i);
        __half2* dst = (__half2*)(xh + (size_t)(t0 + tt) * H);
        dst[2 * i]     = __floats2half2_rn(v.x, v.y);
        dst[2 * i + 1] = __floats2half2_rn(v.z, v.w);
    }
}

// ---------------- capacity scan: block-per-expert, 8 warps ballot in parallel ----------------
__global__ void assign_kernel(int N) {
    const int NK = TOPK * N;                    // 4096
    const int e = blockIdx.x;                   // expert
    const int tid = threadIdx.x;
    const int lane = tid & 31, warp = tid >> 5; // 8 warps

    __shared__ int se[2 * 2048];
    __shared__ int wcnt[8];
    for (int i = tid; i < NK; i += blockDim.x) se[i] = g_entry_expert[i];
    for (int i = tid; i < CAP; i += blockDim.x) g_slot_token[e * CAP + i] = -1;
    __syncthreads();

    const unsigned lt = (1u << lane) - 1u;
    int cnt = 0;
    for (int base = 0; base < NK; base += 256) {
        const int idx = base + warp * 32 + lane;
        const bool match = (se[idx] == e);
        const unsigned m = __ballot_sync(0xffffffffu, match);
        if (lane == 0) wcnt[warp] = __popc(m);
        __syncthreads();
        int wbase = cnt, tot = 0;
        #pragma unroll
        for (int w = 0; w < 8; w++) {
            const int c = wcnt[w];
            if (w < warp) wbase += c;
            tot += c;
        }
        if (match) {
            const int pos = wbase + __popc(m & lt);
            if (pos < CAP) {
                const int d = e * CAP + pos;
                g_slot_token[d] = idx % N;
                g_entry_dest[idx] = d;
            } else {
                g_entry_dest[idx] = -1;
            }
        }
        cnt += tot;
        __syncthreads();
    }
}

// ---------------- FP16 mma.sync GEMM, ldmatrix, 2 CTAs/SM ----------------
// Block 128x128x64, 8 warps (2M x 4N), warp tile 64x32 (4x4 m16n8k16).
// Smem pitch 144: conflict-free ldmatrix phases. 3-stage cp.async pipeline.
// GATHER: A rows from xh[token] via slot->token (dropped -> zerorow).
#define BM 128
#define BN 128
#define BK 64
#define PITCH 144
#define STAGES 3
#define STAGE_BYTES ((BM + BN) * PITCH)          // 36864
#define GEMM_SMEM (STAGES * STAGE_BYTES)         // 110592
#define GTHREADS 256

template<bool GELU, bool GATHER, typename CT>
__global__ __launch_bounds__(GTHREADS, 2)
void gemm_h(const __half* __restrict__ A, const __half* __restrict__ B,
            const float* __restrict__ bias, CT* __restrict__ C,
            int Ncols, int K, const int* __restrict__ slot_token,
            const __half* __restrict__ zerorow) {
    extern __shared__ char smraw[];
    __shared__ int tok[BM];
    const uint32_t sbase = smem_u32(smraw);
    const int tid = threadIdx.x, lane = tid & 31, wid = tid >> 5;
    const int wm = wid & 1, wn = wid >> 1;       // 2(M) x 4(N), warp tile 64x32
    const int bm = blockIdx.y * BM, bn = blockIdx.x * BN;
    const int lr = lane >> 2, lc = lane & 3;
    const int KT = K / BK;

    if (GATHER) {
        if (tid < BM) tok[tid] = slot_token[bm + tid];
        __syncthreads();
    }

    const int lrow = tid >> 3;        // 0..31
    const int lch  = tid & 7;         // 16B chunk in 128B row

    const __half* aRow[4];
    #pragma unroll
    for (int l = 0; l < 4; l++) {
        const int row = lrow + l * 32;
        if (GATHER) {
            const int t = tok[row];
            aRow[l] = (t >= 0) ? A + (size_t)t * K : zerorow;
        } else {
            aRow[l] = A + (size_t)(bm + row) * K;
        }
    }

    float acc[4][4][4];
    #pragma unroll
    for (int i = 0; i < 4; i++)
        #pragma unroll
        for (int j = 0; j < 4; j++)
            #pragma unroll
            for (int q = 0; q < 4; q++) acc[i][j][q] = 0.f;

    const int g = lane >> 3, li = lane & 7;
    const uint32_t aOff = (uint32_t)(wm * 64 + (g & 1) * 8 + li) * PITCH + ((g >> 1) << 4);
    const uint32_t bOff = (uint32_t)(wn * 32 + (g >> 1) * 8 + li) * PITCH + ((g & 1) << 4)
                        + BM * PITCH;

    auto load_stage = [&](int t, int s) {
        const int k0 = t * BK;
        const uint32_t stA = sbase + s * STAGE_BYTES;
        const uint32_t stB = stA + BM * PITCH;
        #pragma unroll
        for (int l = 0; l < 4; l++) {
            const int row = lrow + l * 32;
            cp16(stA + row * PITCH + lch * 16, aRow[l] + k0 + lch * 8);
        }
        #pragma unroll
        for (int l = 0; l < 4; l++) {
            const int row = lrow + l * 32;
            cp16(stB + row * PITCH + lch * 16, B + (size_t)(bn + row) * K + k0 + lch * 8);
        }
    };

    #pragma unroll
    for (int t = 0; t < STAGES - 1; t++) {
        load_stage(t, t);
        asm volatile("cp.async.commit_group;" ::: "memory");
    }

    for (int t = 0; t < KT; t++) {
        asm volatile("cp.async.wait_group %0;" :: "n"(STAGES - 2) : "memory");
        __syncthreads();

        const int tn = t + STAGES - 1;
        if (tn < KT) load_stage(tn, tn % STAGES);
        asm volatile("cp.async.commit_group;" ::: "memory");

        const uint32_t stBase = sbase + (uint32_t)(t % STAGES) * STAGE_BYTES;
        const uint32_t aBase = stBase + aOff;
        const uint32_t bBase = stBase + bOff;

        #pragma unroll
        for (int ks = 0; ks < 4; ks++) {         // four k16 steps per BK=64
            uint32_t a[4][4], b[4][2];
            const uint32_t kb = (uint32_t)ks * 32;
            #pragma unroll
            for (int mt = 0; mt < 4; mt++)
                ldsm_x4(a[mt], aBase + mt * (16 * PITCH) + kb);
            #pragma unroll
            for (int ntp = 0; ntp < 2; ntp++) {
                uint32_t r[4];
                ldsm_x4(r, bBase + ntp * (16 * PITCH) + kb);
                b[2 * ntp][0] = r[0]; b[2 * ntp][1] = r[1];
                b[2 * ntp + 1][0] = r[2]; b[2 * ntp + 1][1] = r[3];
            }
            #pragma unroll
            for (int mt = 0; mt < 4; mt++)
                #pragma unroll
                for (int nt = 0; nt < 4; nt++)
                    mma_f16(acc[mt][nt], a[mt], b[nt]);
        }
    }

    // epilogue: bias (+GELU); CT = __half (GEMM1) or float (GEMM2)
    #pragma unroll
    for (int nt = 0; nt < 4; nt++) {
        const int col = bn + wn * 32 + nt * 8 + 2 * lc;
        const float b0 = __ldg(&bias[col]), b1 = __ldg(&bias[col + 1]);
        #pragma unroll
        for (int mt = 0; mt < 4; mt++) {
            const int row0 = bm + wm * 64 + mt * 16 + lr;
            float v0 = acc[mt][nt][0] + b0;
            float v1 = acc[mt][nt][1] + b1;
            float v2 = acc[mt][nt][2] + b0;
            float v3 = acc[mt][nt][3] + b1;
            if (GELU) {
                v0 = 0.5f * v0 * (1.f + erff(v0 * 0.7071067811865475f));
                v1 = 0.5f * v1 * (1.f + erff(v1 * 0.7071067811865475f));
                v2 = 0.5f * v2 * (1.f + erff(v2 * 0.7071067811865475f));
                v3 = 0.5f * v3 * (1.f + erff(v3 * 0.7071067811865475f));
            }
            if (sizeof(CT) == 2) {
                __half2* c0 = (__half2*)((__half*)C + (size_t)row0 * Ncols + col);
                __half2* c1 = (__half2*)((__half*)C + (size_t)(row0 + 8) * Ncols + col);
                *c0 = __floats2half2_rn(v0, v1);
                *c1 = __floats2half2_rn(v2, v3);
            } else {
                *(float2*)((float*)C + (size_t)row0 * Ncols + col)       = make_float2(v0, v1);
                *(float2*)((float*)C + (size_t)(row0 + 8) * Ncols + col) = make_float2(v2, v3);
            }
        }
    }
}

// ---------------- weighted combine ----------------
__global__ void combine_kernel(int N, float* __restrict__ out) {
    const int t = blockIdx.x;
    const int d0 = g_entry_dest[t];
    const int d1 = g_entry_dest[N + t];
    const float p0 = g_entry_prob[t];
    const float p1 = g_entry_prob[N + t];
    const float4* h0 = (d0 >= 0) ? (const float4*)(g_h + (size_t)d0 * H) : nullptr;
    const float4* h1 = (d1 >= 0) ? (const float4*)(g_h + (size_t)d1 * H) : nullptr;
    float4* o = (float4*)(out + (size_t)t * H);
    for (int i = threadIdx.x; i < H / 4; i += blockDim.x) {
        float4 acc = make_float4(0.f, 0.f, 0.f, 0.f);
        if (h0) { float4 v = h0[i]; acc.x += p0*v.x; acc.y += p0*v.y; acc.z += p0*v.z; acc.w += p0*v.w; }
        if (h1) { float4 v = h1[i]; acc.x += p1*v.x; acc.y += p1*v.y; acc.z += p1*v.z; acc.w += p1*v.w; }
        o[i] = acc;
    }
}

// ---------------- launch ----------------
extern "C" void kernel_launch(void* const* d_in, const int* in_sizes, int n_in,
                              void* d_out, int out_size) {
    const float* x  = (const float*)d_in[0];
    const float* rw = (const float*)d_in[1];
    const float* w1 = (const float*)d_in[2];
    const float* b1 = (const float*)d_in[3];
    const float* w2 = (const float*)d_in[4];
    const float* b2 = (const float*)d_in[5];
    float* out = (float*)d_out;

    const int N = in_sizes[0] / H;   // 2048

    __half* xh;   cudaGetSymbolAddress((void**)&xh, g_xh);
    __half* acth; cudaGetSymbolAddress((void**)&acth, g_acth);
    __half* w1h;  cudaGetSymbolAddress((void**)&w1h, g_w1h);
    __half* w2h;  cudaGetSymbolAddress((void**)&w2h, g_w2h);
    float*  hbf;  cudaGetSymbolAddress((void**)&hbf, g_h);
    __half* zrow; cudaGetSymbolAddress((void**)&zrow, g_zerorow);
    int*   stok;  cudaGetSymbolAddress((void**)&stok, g_slot_token);

    cudaFuncSetAttribute(router_kernel,
                         cudaFuncAttributeMaxDynamicSharedMemorySize, ROUTER_SMEM);
    cudaFuncSetAttribute(gemm_h<true, true, __half>,
                         cudaFuncAttributeMaxDynamicSharedMemorySize, GEMM_SMEM);
    cudaFuncSetAttribute(gemm_h<false, false, float>,
                         cudaFuncAttributeMaxDynamicSharedMemorySize, GEMM_SMEM);

    {   // weight fp16 conversions
        size_t n4 = (size_t)F * H / 4;
        tohalf<<<(unsigned)((n4 + 255) / 256), 256>>>(w1, w1h, n4);
        tohalf<<<(unsigned)((n4 + 255) / 256), 256>>>(w2, w2h, n4);
    }

    router_kernel<<<N / RT, 256, ROUTER_SMEM>>>(x, rw, xh, N);
    assign_kernel<<<E, 256>>>(N);

    // GEMM1 (gather A from xh via slot->token): -> gelu -> act (fp16)
    gemm_h<true, true, __half><<<dim3(F / BN, NSLOT / BM), GTHREADS, GEMM_SMEM>>>(
        xh, w1h, b1, acth, F, H, stok, zrow);
    // GEMM2: act[4096,8192] @ w2h^T + b2 -> h (fp32)
    gemm_h<false, false, float><<<dim3(H / BN, NSLOT / BM), GTHREADS, GEMM_SMEM>>>(
        acth, w2h, b2, hbf, H, F, nullptr, nullptr);

    combine_kernel<<<N, 256>>>(N, out);
}

// round 16
// speedup vs baseline: 1.0703x; 1.0703x over previous
#include <cuda_runtime.h>
#include <cuda_fp16.h>
#include <cstdint>
#include <math.h>

#define E 8
#define TOPK 2
#define CAP 512
#define H 2048
#define F 8192
#define NSLOT (E*CAP)   // 4096

// ---------------- scratch (no allocation allowed) ----------------
__device__ __half g_xh[(size_t)2048 * H];     // fp16 copy of tokens
__device__ __half g_acth[(size_t)NSLOT * F];  // gelu acts fp16
__device__ __half g_w1h[(size_t)F * H];       // w1 fp16
__device__ __half g_w2h[(size_t)H * F];       // w2 fp16
__device__ float  g_h[(size_t)NSLOT * H];     // expert output fp32
__device__ __half g_zerorow[H];               // zero A-row for dropped slots
__device__ int    g_entry_expert[2 * 2048];
__device__ float  g_entry_prob  [2 * 2048];
__device__ int    g_entry_dest  [2 * 2048];   // dest slot or -1 (for combine)
__device__ int    g_slot_token  [NSLOT];      // token feeding each slot, or -1

// ---------------- helpers ----------------
__device__ __forceinline__ uint32_t smem_u32(const void* p) {
    uint32_t a;
    asm("{ .reg .u64 t; cvta.to.shared.u64 t, %1; cvt.u32.u64 %0, t; }"
        : "=r"(a) : "l"(p));
    return a;
}
__device__ __forceinline__ void cp16(uint32_t dst, const void* src) {
    asm volatile("cp.async.cg.shared.global [%0], [%1], 16;"
                 :: "r"(dst), "l"(src) : "memory");
}
__device__ __forceinline__ void ldsm_x4(uint32_t* r, uint32_t addr) {
    asm volatile("ldmatrix.sync.aligned.m8n8.x4.shared.b16 {%0,%1,%2,%3}, [%4];"
                 : "=r"(r[0]), "=r"(r[1]), "=r"(r[2]), "=r"(r[3]) : "r"(addr));
}
__device__ __forceinline__ void mma_f16(float* c, const uint32_t* a, const uint32_t* b) {
    asm volatile(
        "mma.sync.aligned.m16n8k16.row.col.f32.f16.f16.f32 "
        "{%0,%1,%2,%3}, {%4,%5,%6,%7}, {%8,%9}, {%0,%1,%2,%3};"
        : "+f"(c[0]), "+f"(c[1]), "+f"(c[2]), "+f"(c[3])
        : "r"(a[0]), "r"(a[1]), "r"(a[2]), "r"(a[3]), "r"(b[0]), "r"(b[1]));
}

// ---------------- fp32 -> fp16 conversion pass (weights) ----------------
__global__ void tohalf(const float* __restrict__ src, __half* __restrict__ dst,
                       size_t n4) {
    size_t i = (size_t)blockIdx.x * blockDim.x + threadIdx.x;
    if (i < n4) {
        float4 v = ((const float4*)src)[i];
        ((__half2*)dst)[2 * i]     = __floats2half2_rn(v.x, v.y);
        ((__half2*)dst)[2 * i + 1] = __floats2half2_rn(v.z, v.w);
    }
}

// ---------------- router (r13 version: block per token, fp16 writeback) ----------------
__global__ void router_kernel(const float* __restrict__ x,
                              const float* __restrict__ rw,
                              __half* __restrict__ xh, int N) {
    const int t = blockIdx.x;
    const int tid = threadIdx.x;
    const int lane = tid & 31, warp = tid >> 5;

    __shared__ float xs[H];
    const float4* xv = (const float4*)(x + (size_t)t * H);
    float4* xsv = (float4*)xs;
    for (int i = tid; i < H / 4; i += 256) xsv[i] = xv[i];
    __syncthreads();

    // fp16 writeback from smem
    {
        __half2* dst = (__half2*)(xh + (size_t)t * H);
        for (int i = tid; i < H / 4; i += 256) {
            float4 v = xsv[i];
            dst[2 * i]     = __floats2half2_rn(v.x, v.y);
            dst[2 * i + 1] = __floats2half2_rn(v.z, v.w);
        }
    }

    const float* wr = rw + (size_t)warp * H;
    float s = 0.f;
    for (int i = lane; i < H; i += 32) s += xs[i] * wr[i];
    #pragma unroll
    for (int o = 16; o; o >>= 1) s += __shfl_xor_sync(0xffffffffu, s, o);

    __shared__ float logits[E];
    if (lane == 0) logits[warp] = s;
    __syncthreads();

    if (tid == 0) {
        float m = logits[0];
        #pragma unroll
        for (int e = 1; e < E; e++) m = fmaxf(m, logits[e]);
        float p[E], den = 0.f;
        #pragma unroll
        for (int e = 0; e < E; e++) { p[e] = __expf(logits[e] - m); den += p[e]; }
        float inv = 1.f / den;
        #pragma unroll
        for (int e = 0; e < E; e++) p[e] *= inv;
        int i0 = 0;
        #pragma unroll
        for (int e = 1; e < E; e++) if (p[e] > p[i0]) i0 = e;
        int i1 = (i0 == 0) ? 1 : 0;
        #pragma unroll
        for (int e = 0; e < E; e++) if (e != i0 && p[e] > p[i1]) i1 = e;
        g_entry_expert[t]     = i0; g_entry_prob[t]     = p[i0];
        g_entry_expert[N + t] = i1; g_entry_prob[N + t] = p[i1];
    }
}

// ---------------- capacity scan: block-per-expert, 8 warps ballot in parallel ----------------
__global__ void assign_kernel(int N) {
    const int NK = TOPK * N;                    // 4096
    const int e = blockIdx.x;                   // expert
    const int tid = threadIdx.x;
    const int lane = tid & 31, warp = tid >> 5; // 8 warps

    __shared__ int se[2 * 2048];
    __shared__ int wcnt[8];
    for (int i = tid; i < NK; i += blockDim.x) se[i] = g_entry_expert[i];
    for (int i = tid; i < CAP; i += blockDim.x) g_slot_token[e * CAP + i] = -1;
    __syncthreads();

    const unsigned lt = (1u << lane) - 1u;
    int cnt = 0;
    for (int base = 0; base < NK; base += 256) {
        const int idx = base + warp * 32 + lane;
        const bool match = (se[idx] == e);
        const unsigned m = __ballot_sync(0xffffffffu, match);
        if (lane == 0) wcnt[warp] = __popc(m);
        __syncthreads();
        int wbase = cnt, tot = 0;
        #pragma unroll
        for (int w = 0; w < 8; w++) {
            const int c = wcnt[w];
            if (w < warp) wbase += c;
            tot += c;
        }
        if (match) {
            const int pos = wbase + __popc(m & lt);
            if (pos < CAP) {
                const int d = e * CAP + pos;
                g_slot_token[d] = idx % N;
                g_entry_dest[idx] = d;
            } else {
                g_entry_dest[idx] = -1;
            }
        }
        cnt += tot;
        __syncthreads();
    }
}

// ---------------- FP16 mma.sync GEMM, ldmatrix, 2 CTAs/SM ----------------
// Block 128x128x64, 8 warps (2M x 4N), warp tile 64x32 (4x4 m16n8k16).
// Smem pitch 144: conflict-free ldmatrix phases. 3-stage cp.async pipeline.
// GATHER: A rows from xh[token] via slot->token (dropped -> zerorow).
#define BM 128
#define BN 128
#define BK 64
#define PITCH 144
#define STAGES 3
#define STAGE_BYTES ((BM + BN) * PITCH)          // 36864
#define GEMM_SMEM (STAGES * STAGE_BYTES)         // 110592
#define GTHREADS 256

template<bool GELU, bool GATHER, typename CT>
__global__ __launch_bounds__(GTHREADS, 2)
void gemm_h(const __half* __restrict__ A, const __half* __restrict__ B,
            const float* __restrict__ bias, CT* __restrict__ C,
            int Ncols, int K, const int* __restrict__ slot_token,
            const __half* __restrict__ zerorow) {
    extern __shared__ char smraw[];
    __shared__ int tok[BM];
    const uint32_t sbase = smem_u32(smraw);
    const int tid = threadIdx.x, lane = tid & 31, wid = tid >> 5;
    const int wm = wid & 1, wn = wid >> 1;       // 2(M) x 4(N), warp tile 64x32
    const int bm = blockIdx.y * BM, bn = blockIdx.x * BN;
    const int lr = lane >> 2, lc = lane & 3;
    const int KT = K / BK;

    if (GATHER) {
        if (tid < BM) tok[tid] = slot_token[bm + tid];
        __syncthreads();
    }

    const int lrow = tid >> 3;        // 0..31
    const int lch  = tid & 7;         // 16B chunk in 128B row

    const __half* aRow[4];
    #pragma unroll
    for (int l = 0; l < 4; l++) {
        const int row = lrow + l * 32;
        if (GATHER) {
            const int t = tok[row];
            aRow[l] = (t >= 0) ? A + (size_t)t * K : zerorow;
        } else {
            aRow[l] = A + (size_t)(bm + row) * K;
        }
    }

    float acc[4][4][4];
    #pragma unroll
    for (int i = 0; i < 4; i++)
        #pragma unroll
        for (int j = 0; j < 4; j++)
            #pragma unroll
            for (int q = 0; q < 4; q++) acc[i][j][q] = 0.f;

    const int g = lane >> 3, li = lane & 7;
    const uint32_t aOff = (uint32_t)(wm * 64 + (g & 1) * 8 + li) * PITCH + ((g >> 1) << 4);
    const uint32_t bOff = (uint32_t)(wn * 32 + (g >> 1) * 8 + li) * PITCH + ((g & 1) << 4)
                        + BM * PITCH;

    auto load_stage = [&](int t, int s) {
        const int k0 = t * BK;
        const uint32_t stA = sbase + s * STAGE_BYTES;
        const uint32_t stB = stA + BM * PITCH;
        #pragma unroll
        for (int l = 0; l < 4; l++) {
            const int row = lrow + l * 32;
            cp16(stA + row * PITCH + lch * 16, aRow[l] + k0 + lch * 8);
        }
        #pragma unroll
        for (int l = 0; l < 4; l++) {
            const int row = lrow + l * 32;
            cp16(stB + row * PITCH + lch * 16, B + (size_t)(bn + row) * K + k0 + lch * 8);
        }
    };

    #pragma unroll
    for (int t = 0; t < STAGES - 1; t++) {
        load_stage(t, t);
        asm volatile("cp.async.commit_group;" ::: "memory");
    }

    for (int t = 0; t < KT; t++) {
        asm volatile("cp.async.wait_group %0;" :: "n"(STAGES - 2) : "memory");
        __syncthreads();

        const int tn = t + STAGES - 1;
        if (tn < KT) load_stage(tn, tn % STAGES);
        asm volatile("cp.async.commit_group;" ::: "memory");

        const uint32_t stBase = sbase + (uint32_t)(t % STAGES) * STAGE_BYTES;
        const uint32_t aBase = stBase + aOff;
        const uint32_t bBase = stBase + bOff;

        #pragma unroll
        for (int ks = 0; ks < 4; ks++) {         // four k16 steps per BK=64
            uint32_t a[4][4], b[4][2];
            const uint32_t kb = (uint32_t)ks * 32;
            #pragma unroll
            for (int mt = 0; mt < 4; mt++)
                ldsm_x4(a[mt], aBase + mt * (16 * PITCH) + kb);
            #pragma unroll
            for (int ntp = 0; ntp < 2; ntp++) {
                uint32_t r[4];
                ldsm_x4(r, bBase + ntp * (16 * PITCH) + kb);
                b[2 * ntp][0] = r[0]; b[2 * ntp][1] = r[1];
                b[2 * ntp + 1][0] = r[2]; b[2 * ntp + 1][1] = r[3];
            }
            #pragma unroll
            for (int mt = 0; mt < 4; mt++)
                #pragma unroll
                for (int nt = 0; nt < 4; nt++)
                    mma_f16(acc[mt][nt], a[mt], b[nt]);
        }
    }

    // epilogue: bias (+GELU); CT = __half (GEMM1) or float (GEMM2)
    #pragma unroll
    for (int nt = 0; nt < 4; nt++) {
        const int col = bn + wn * 32 + nt * 8 + 2 * lc;
        const float b0 = __ldg(&bias[col]), b1 = __ldg(&bias[col + 1]);
        #pragma unroll
        for (int mt = 0; mt < 4; mt++) {
            const int row0 = bm + wm * 64 + mt * 16 + lr;
            float v0 = acc[mt][nt][0] + b0;
            float v1 = acc[mt][nt][1] + b1;
            float v2 = acc[mt][nt][2] + b0;
            float v3 = acc[mt][nt][3] + b1;
            if (GELU) {
                v0 = 0.5f * v0 * (1.f + erff(v0 * 0.7071067811865475f));
                v1 = 0.5f * v1 * (1.f + erff(v1 * 0.7071067811865475f));
                v2 = 0.5f * v2 * (1.f + erff(v2 * 0.7071067811865475f));
                v3 = 0.5f * v3 * (1.f + erff(v3 * 0.7071067811865475f));
            }
            if (sizeof(CT) == 2) {
                __half2* c0 = (__half2*)((__half*)C + (size_t)row0 * Ncols + col);
                __half2* c1 = (__half2*)((__half*)C + (size_t)(row0 + 8) * Ncols + col);
                *c0 = __floats2half2_rn(v0, v1);
                *c1 = __floats2half2_rn(v2, v3);
            } else {
                *(float2*)((float*)C + (size_t)row0 * Ncols + col)       = make_float2(v0, v1);
                *(float2*)((float*)C + (size_t)(row0 + 8) * Ncols + col) = make_float2(v2, v3);
            }
        }
    }
}

// ---------------- weighted combine ----------------
__global__ void combine_kernel(int N, float* __restrict__ out) {
    const int t = blockIdx.x;
    const int d0 = g_entry_dest[t];
    const int d1 = g_entry_dest[N + t];
    const float p0 = g_entry_prob[t];
    const float p1 = g_entry_prob[N + t];
    const float4* h0 = (d0 >= 0) ? (const float4*)(g_h + (size_t)d0 * H) : nullptr;
    const float4* h1 = (d1 >= 0) ? (const float4*)(g_h + (size_t)d1 * H) : nullptr;
    float4* o = (float4*)(out + (size_t)t * H);
    for (int i = threadIdx.x; i < H / 4; i += blockDim.x) {
        float4 acc = make_float4(0.f, 0.f, 0.f, 0.f);
        if (h0) { float4 v = h0[i]; acc.x += p0*v.x; acc.y += p0*v.y; acc.z += p0*v.z; acc.w += p0*v.w; }
        if (h1) { float4 v = h1[i]; acc.x += p1*v.x; acc.y += p1*v.y; acc.z += p1*v.z; acc.w += p1*v.w; }
        o[i] = acc;
    }
}

// ---------------- launch ----------------
extern "C" void kernel_launch(void* const* d_in, const int* in_sizes, int n_in,
                              void* d_out, int out_size) {
    const float* x  = (const float*)d_in[0];
    const float* rw = (const float*)d_in[1];
    const float* w1 = (const float*)d_in[2];
    const float* b1 = (const float*)d_in[3];
    const float* w2 = (const float*)d_in[4];
    const float* b2 = (const float*)d_in[5];
    float* out = (float*)d_out;

    const int N = in_sizes[0] / H;   // 2048

    __half* xh;   cudaGetSymbolAddress((void**)&xh, g_xh);
    __half* acth; cudaGetSymbolAddress((void**)&acth, g_acth);
    __half* w1h;  cudaGetSymbolAddress((void**)&w1h, g_w1h);
    __half* w2h;  cudaGetSymbolAddress((void**)&w2h, g_w2h);
    float*  hbf;  cudaGetSymbolAddress((void**)&hbf, g_h);
    __half* zrow; cudaGetSymbolAddress((void**)&zrow, g_zerorow);
    int*   stok;  cudaGetSymbolAddress((void**)&stok, g_slot_token);

    cudaFuncSetAttribute(gemm_h<true, true, __half>,
                         cudaFuncAttributeMaxDynamicSharedMemorySize, GEMM_SMEM);
    cudaFuncSetAttribute(gemm_h<false, false, float>,
                         cudaFuncAttributeMaxDynamicSharedMemorySize, GEMM_SMEM);

    {   // weight fp16 conversions
        size_t n4 = (size_t)F * H / 4;
        tohalf<<<(unsigned)((n4 + 255) / 256), 256>>>(w1, w1h, n4);
        tohalf<<<(unsigned)((n4 + 255) / 256), 256>>>(w2, w2h, n4);
    }

    router_kernel<<<N, 256>>>(x, rw, xh, N);
    assign_kernel<<<E, 256>>>(N);

    // GEMM1 (gather A from xh via slot->token): -> gelu -> act (fp16)
    gemm_h<true, true, __half><<<dim3(F / BN, NSLOT / BM), GTHREADS, GEMM_SMEM>>>(
        xh, w1h, b1, acth, F, H, stok, zrow);
    // GEMM2: act[4096,8192] @ w2h^T + b2 -> h (fp32)
    gemm_h<false, false, float><<<dim3(H / BN, NSLOT / BM), GTHREADS, GEMM_SMEM>>>(
        acth, w2h, b2, hbf, H, F, nullptr, nullptr);

    combine_kernel<<<N, 256>>>(N, out);
}